// round 16
// baseline (speedup 1.0000x reference)
#include <cuda_runtime.h>
#include <cuda_bf16.h>

#define BB   32
#define NN   16384
#define DD   64
#define KK   64
#define CPB  8
#define NCTA (BB*CPB)                 // 256 (phase 1)
#define NT   512
#define NW   16
#define PTS  2048                     // points per phase-1 CTA
#define CROW 65                       // padded center row
#define LMAX 3                        // tier-1 max lag
#define KD   16                       // dense rounds: k = 1..KD in phase 1
#define NT2  1024                     // phase-2 threads (1 CTA per batch)
#define NW2  32
#define PPT2 (NN/NT2)                 // 16

// phase-2 dynamic SMEM: ub + centers + staged pts + worklist + lk
#define SMEM2_BYTES (NN*4 + KK*CROW*4 + NW2*DD*4 + NN*2 + NN)   // 139520

// ---------------- device globals (static scratch only) --------------------
__device__ unsigned long long g_part[BB * KK * CPB];  // phase-1 round barrier
__device__ float              g_ub[BB * NN];          // phase handoff (2 MB)

__global__ void km_init() {
    int i = blockIdx.x * blockDim.x + threadIdx.x;
    if (i < BB * KK * CPB) g_part[i] = 0ULL;
}

// 32-byte read-only global loads (256-bit). Bits land unchanged.
__device__ __forceinline__ void ld256(const float* p, float4& a, float4& b) {
    unsigned long long x, y, z, w;
    asm("ld.global.nc.v4.b64 {%0,%1,%2,%3}, [%4];"
        : "=l"(x), "=l"(y), "=l"(z), "=l"(w) : "l"(p));
    a.x = __uint_as_float((unsigned)x);  a.y = __uint_as_float((unsigned)(x >> 32));
    a.z = __uint_as_float((unsigned)y);  a.w = __uint_as_float((unsigned)(y >> 32));
    b.x = __uint_as_float((unsigned)z);  b.y = __uint_as_float((unsigned)(z >> 32));
    b.z = __uint_as_float((unsigned)w);  b.w = __uint_as_float((unsigned)(w >> 32));
}
__device__ __forceinline__ void ld256_el(const float* p, float4& a, float4& b) {
    unsigned long long x, y, z, w;
    asm("ld.global.nc.L2::evict_last.v4.b64 {%0,%1,%2,%3}, [%4];"
        : "=l"(x), "=l"(y), "=l"(z), "=l"(w) : "l"(p));
    a.x = __uint_as_float((unsigned)x);  a.y = __uint_as_float((unsigned)(x >> 32));
    a.z = __uint_as_float((unsigned)y);  a.w = __uint_as_float((unsigned)(y >> 32));
    b.x = __uint_as_float((unsigned)z);  b.y = __uint_as_float((unsigned)(z >> 32));
    b.z = __uint_as_float((unsigned)w);  b.w = __uint_as_float((unsigned)(w >> 32));
}

// ---- THE distance: R1's PROVEN rounding order (rel_err 0.0 since R7).
// Four sequential 16-dim fmaf chains, combined ((s0+s1)+s2)+s3.
__device__ __forceinline__ float dist16x4_g(const float* __restrict__ px,
                                            const float* __restrict__ cen) {
    float s[4];
    #pragma unroll
    for (int g = 0; g < 4; ++g) {
        float4 v0, v1, v2, v3;
        ld256(px + g * 16,     v0, v1);
        ld256(px + g * 16 + 8, v2, v3);
        const int b = g * 16;
        float acc = 0.f, d;
        d = v0.x - cen[b + 0];  acc = fmaf(d, d, acc);
        d = v0.y - cen[b + 1];  acc = fmaf(d, d, acc);
        d = v0.z - cen[b + 2];  acc = fmaf(d, d, acc);
        d = v0.w - cen[b + 3];  acc = fmaf(d, d, acc);
        d = v1.x - cen[b + 4];  acc = fmaf(d, d, acc);
        d = v1.y - cen[b + 5];  acc = fmaf(d, d, acc);
        d = v1.z - cen[b + 6];  acc = fmaf(d, d, acc);
        d = v1.w - cen[b + 7];  acc = fmaf(d, d, acc);
        d = v2.x - cen[b + 8];  acc = fmaf(d, d, acc);
        d = v2.y - cen[b + 9];  acc = fmaf(d, d, acc);
        d = v2.z - cen[b + 10]; acc = fmaf(d, d, acc);
        d = v2.w - cen[b + 11]; acc = fmaf(d, d, acc);
        d = v3.x - cen[b + 12]; acc = fmaf(d, d, acc);
        d = v3.y - cen[b + 13]; acc = fmaf(d, d, acc);
        d = v3.z - cen[b + 14]; acc = fmaf(d, d, acc);
        d = v3.w - cen[b + 15]; acc = fmaf(d, d, acc);
        s[g] = acc;
    }
    return ((s[0] + s[1]) + s[2]) + s[3];
}
__device__ __forceinline__ float dist16x4_s(const float* __restrict__ pt,
                                            const float* __restrict__ cen) {
    float s[4];
    #pragma unroll
    for (int g = 0; g < 4; ++g) {
        float acc = 0.f;
        #pragma unroll
        for (int i = 0; i < 16; ++i) {
            float d = pt[g * 16 + i] - cen[g * 16 + i];
            acc = fmaf(d, d, acc);
        }
        s[g] = acc;
    }
    return ((s[0] + s[1]) + s[2]) + s[3];
}

__device__ __forceinline__ unsigned long long warp_max_u64(unsigned long long v) {
    #pragma unroll
    for (int o = 16; o; o >>= 1) {
        unsigned long long u = __shfl_xor_sync(0xffffffffu, v, o);
        v = (v > u) ? v : u;
    }
    return v;
}
__device__ __forceinline__ float warp_min_f(float m) {
    #pragma unroll
    for (int o = 16; o; o >>= 1) m = fminf(m, __shfl_xor_sync(0xffffffffu, m, o));
    return m;
}

// dense-round body: one point (8-lane tile slot), one 16-dim group per lane
#define DENSE_BODY(LOADER)                                                   \
    {                                                                        \
        const float* px = wbase + (size_t)pt * DD + g * 16;                  \
        float4 v0, v1, v2, v3;                                               \
        LOADER(px,     v0, v1);                                              \
        LOADER(px + 8, v2, v3);                                              \
        float acc = 0.f, d;                                                  \
        d = v0.x - cg[0];  acc = fmaf(d, d, acc);                            \
        d = v0.y - cg[1];  acc = fmaf(d, d, acc);                            \
        d = v0.z - cg[2];  acc = fmaf(d, d, acc);                            \
        d = v0.w - cg[3];  acc = fmaf(d, d, acc);                            \
        d = v1.x - cg[4];  acc = fmaf(d, d, acc);                            \
        d = v1.y - cg[5];  acc = fmaf(d, d, acc);                            \
        d = v1.z - cg[6];  acc = fmaf(d, d, acc);                            \
        d = v1.w - cg[7];  acc = fmaf(d, d, acc);                            \
        d = v2.x - cg[8];  acc = fmaf(d, d, acc);                            \
        d = v2.y - cg[9];  acc = fmaf(d, d, acc);                            \
        d = v2.z - cg[10]; acc = fmaf(d, d, acc);                            \
        d = v2.w - cg[11]; acc = fmaf(d, d, acc);                            \
        d = v3.x - cg[12]; acc = fmaf(d, d, acc);                            \
        d = v3.y - cg[13]; acc = fmaf(d, d, acc);                            \
        d = v3.z - cg[14]; acc = fmaf(d, d, acc);                            \
        d = v3.w - cg[15]; acc = fmaf(d, d, acc);                            \
        float s0 = __shfl_sync(0xffffffffu, acc, lb + 0);                    \
        float s1 = __shfl_sync(0xffffffffu, acc, lb + 1);                    \
        float s2 = __shfl_sync(0xffffffffu, acc, lb + 2);                    \
        float s3 = __shfl_sync(0xffffffffu, acc, lb + 3);                    \
        float s  = ((s0 + s1) + s2) + s3;                                    \
        if (g == 0) {                                                        \
            int p = wid * 128 + pt;                                          \
            float m = fminf(s_ub[p], s);                                     \
            s_ub[p] = m;                                                     \
            unsigned long long pk =                                          \
                ((unsigned long long)__float_as_uint(m) << 32) |             \
                (unsigned)~(pbase + p);                                      \
            best = (best > pk) ? best : pk;                                  \
        }                                                                    \
    }

// ===================== PHASE 1: dense rounds k = 1..KD =====================
__global__ void __launch_bounds__(NT, 2)
kmpp_phase1(const float* __restrict__ data,
            const int*   __restrict__ first_idx,
            float*       __restrict__ out)
{
    __shared__ float s_c[KD + 1][CROW];
    __shared__ __align__(16) float s_ub[PTS];
    __shared__ unsigned long long s_red[NW];
    __shared__ unsigned long long s_parts[CPB];
    __shared__ int s_widx;

    const int t     = threadIdx.x;
    const int lane  = t & 31;
    const int wid   = t >> 5;
    const int cta   = blockIdx.x;
    const int batch = cta / CPB;
    const int chunk = cta % CPB;
    const int pbase = chunk * PTS;
    const float* bd = data + (size_t)batch * NN * DD;
    float* bout     = out  + (size_t)batch * KK * DD;
    const bool leader = (chunk == 0);

    if (t < DD) {
        int i0 = first_idx[batch];
        float c = bd[(size_t)i0 * DD + t];
        s_c[0][t] = c;
        if (leader) bout[t] = c;
    }
    #pragma unroll
    for (int j = 0; j < 4; ++j) s_ub[t * 4 + j] = 3.4e38f;
    __syncthreads();

    const int pl = lane >> 2;          // point slot 0..7
    const int g  = lane & 3;           // dim group 0..3
    const int lb = lane & ~3;
    const float* wbase = bd + (size_t)(pbase + wid * 128) * DD;

    for (int k = 1; k <= KD; ++k) {
        const float* cen = &s_c[k - 1][g * 16];
        float cg[16];
        #pragma unroll
        for (int i = 0; i < 16; ++i) cg[i] = cen[i];

        unsigned long long best = 0ULL;
        // iterations 0..9: L2-pinned portion (~62% of dataset, 80MB < L2)
        #pragma unroll 2
        for (int it = 0; it < 10; ++it) {
            const int pt = it * 8 + pl;
            DENSE_BODY(ld256_el)
        }
        // iterations 10..15: streaming portion
        #pragma unroll 2
        for (int it = 10; it < 16; ++it) {
            const int pt = it * 8 + pl;
            DENSE_BODY(ld256)
        }
        best = warp_max_u64(best);
        if (lane == 0) s_red[wid] = best;
        __syncthreads();

        // single-word broadcast barrier across the batch's 8 CTAs
        if (t == 0) {
            unsigned long long b = s_red[0];
            #pragma unroll
            for (int i = 1; i < NW; ++i) b = (b > s_red[i]) ? b : s_red[i];
            atomicExch(&g_part[(batch * KK + k) * CPB + chunk], b);
        }
        if (t < CPB) {
            volatile unsigned long long* sp =
                (volatile unsigned long long*)&g_part[(batch * KK + k) * CPB + t];
            unsigned long long v;
            while ((v = *sp) == 0ULL) { __nanosleep(32); }
            s_parts[t] = v;
        }
        __syncthreads();
        if (t == 0) {
            unsigned long long b = s_parts[0];
            #pragma unroll
            for (int i = 1; i < CPB; ++i) b = (b > s_parts[i]) ? b : s_parts[i];
            s_widx = (int)(~(unsigned)b);
        }
        __syncthreads();

        int w = s_widx;
        if (t < DD) {
            float c = bd[(size_t)w * DD + t];
            s_c[k][t] = c;
            if (leader) bout[k * DD + t] = c;
        }
        if (t == NT - 1) {
            int wl = w - pbase;
            if (wl >= 0 && wl < PTS) s_ub[wl] = 0.f;   // winner marker
        }
        __syncthreads();
    }

    // handoff: ub accounts centers 0..KD-1; winners are ub==0
    #pragma unroll
    for (int j = 0; j < 4; ++j)
        g_ub[batch * NN + pbase + t * 4 + j] = s_ub[t * 4 + j];
}

// ============== PHASE 2: filtered rounds, one CTA per batch ================
__global__ void __launch_bounds__(NT2, 1)
kmpp_phase2(const float* __restrict__ data,
            float*       __restrict__ out)
{
    extern __shared__ float dsm[];
    float* s_ub = dsm;                                   // NN floats
    float* s_c  = dsm + NN;                              // KK*CROW floats
    float* s_pt = s_c + KK * CROW;                       // NW2*DD floats
    short* s_work = (short*)(s_pt + NW2 * DD);           // NN shorts
    unsigned char* s_lk = (unsigned char*)(s_work + NN); // NN bytes
    __shared__ unsigned long long s_red[NW2];
    __shared__ unsigned long long s_t2;
    __shared__ unsigned int s_Ebits;
    __shared__ int s_widx, s_wcnt;

    const int t     = threadIdx.x;
    const int lane  = t & 31;
    const int wid   = t >> 5;
    const int batch = blockIdx.x;
    const float* bd = data + (size_t)batch * NN * DD;
    float* bout     = out  + (size_t)batch * KK * DD;

    // load centers 0..KD (written by phase 1) and the handoff bounds
    for (int i = t; i < (KD + 1) * DD; i += NT2) {
        int kk = i >> 6, dd = i & 63;
        s_c[kk * CROW + dd] = bout[i];
    }
    for (int p = t; p < NN; p += NT2) {
        float u = g_ub[batch * NN + p];
        s_ub[p] = u;
        s_lk[p] = (u == 0.f) ? (unsigned char)KK : (unsigned char)KD;
    }
    __syncthreads();

    for (int k = KD + 1; k < KK; ++k) {
        if (t == 0) { s_Ebits = 0u; s_wcnt = 0; s_t2 = 0ULL; }
        __syncthreads();

        // (B) per-warp candidate: refresh the warp's max-ub point exactly.
        //     E = max of 32 exact min_d values <= round winner value.
        {
            int base = wid * 512 + lane * 16;
            unsigned long long wb = 0ULL;
            #pragma unroll
            for (int q = 0; q < 4; ++q) {
                float4 u = *(const float4*)&s_ub[base + q * 4];
                int bi = base + q * 4;
                unsigned long long p0 = ((unsigned long long)__float_as_uint(u.x) << 32) | (unsigned)~(bi + 0);
                unsigned long long p1 = ((unsigned long long)__float_as_uint(u.y) << 32) | (unsigned)~(bi + 1);
                unsigned long long p2 = ((unsigned long long)__float_as_uint(u.z) << 32) | (unsigned)~(bi + 2);
                unsigned long long p3 = ((unsigned long long)__float_as_uint(u.w) << 32) | (unsigned)~(bi + 3);
                wb = wb > p0 ? wb : p0;
                wb = wb > p1 ? wb : p1;
                wb = wb > p2 ? wb : p2;
                wb = wb > p3 ? wb : p3;
            }
            wb = warp_max_u64(wb);
            int p = (int)(~(unsigned)wb) & (NN - 1);

            if (lane < 16)
                ((float4*)&s_pt[wid * DD])[lane] =
                    __ldg(((const float4*)(bd + (size_t)p * DD)) + lane);
            __syncwarp();

            int   clk = s_lk[p];
            float m   = s_ub[p];
            for (int c = clk + lane; c < k; c += 32)
                m = fminf(m, dist16x4_s(&s_pt[wid * DD], &s_c[c * CROW]));
            m = warp_min_f(m);
            if (lane == 0) {
                s_ub[p] = m;
                if (clk < k) s_lk[p] = (unsigned char)k;
                atomicMax(&s_Ebits, __float_as_uint(m));
            }
        }
        __syncthreads();
        const float E = __uint_as_float(s_Ebits);

        // (C1) classify + tier-1 catch-up, fused with packed argmax.
        unsigned long long best = 0ULL;
        #pragma unroll
        for (int j = 0; j < PPT2; ++j) {
            int p = t * PPT2 + j;
            float m = s_ub[p];
            int   c = s_lk[p];
            bool include = true;
            if (m >= E && c < k) {
                if (k - c <= LMAX) {
                    const float* px = bd + (size_t)p * DD;
                    for (; c < k; ++c)
                        m = fminf(m, dist16x4_g(px, &s_c[c * CROW]));
                    s_ub[p] = m;
                    s_lk[p] = (unsigned char)k;
                } else {
                    int w = atomicAdd(&s_wcnt, 1);
                    s_work[w] = (short)p;
                    include = false;
                }
            }
            if (include) {
                unsigned long long pk =
                    ((unsigned long long)__float_as_uint(m) << 32) | (unsigned)~p;
                best = (best > pk) ? best : pk;
            }
        }
        best = warp_max_u64(best);
        if (lane == 0) s_red[wid] = best;
        __syncthreads();

        // (C2) tier-2: warp per point, lane per center; exact max -> s_t2
        const int W = s_wcnt;
        for (int i = wid; i < W; i += NW2) {
            int p = s_work[i];
            if (lane < 16)
                ((float4*)&s_pt[wid * DD])[lane] =
                    __ldg(((const float4*)(bd + (size_t)p * DD)) + lane);
            __syncwarp();
            int   clk = s_lk[p];
            float m   = s_ub[p];
            for (int c = clk + lane; c < k; c += 32)
                m = fminf(m, dist16x4_s(&s_pt[wid * DD], &s_c[c * CROW]));
            m = warp_min_f(m);
            if (lane == 0) {
                s_ub[p] = m; s_lk[p] = (unsigned char)k;
                unsigned long long pk =
                    ((unsigned long long)__float_as_uint(m) << 32) | (unsigned)~p;
                atomicMax(&s_t2, pk);
            }
            __syncwarp();
        }
        __syncthreads();

        if (t == 0) {
            unsigned long long b = s_red[0];
            #pragma unroll
            for (int i = 1; i < NW2; ++i) b = (b > s_red[i]) ? b : s_red[i];
            unsigned long long v2 = s_t2;
            b = (b > v2) ? b : v2;
            s_widx = (int)(~(unsigned)b);
        }
        __syncthreads();

        int w = s_widx;
        if (t < DD) {
            float c = bd[(size_t)w * DD + t];
            s_c[k * CROW + t] = c;
            bout[k * DD + t] = c;
        }
        if (t == NT2 - 1) { s_ub[w] = 0.f; s_lk[w] = (unsigned char)KK; }
        __syncthreads();
    }
}

extern "C" void kernel_launch(void* const* d_in, const int* in_sizes, int n_in,
                              void* d_out, int out_size) {
    const float* data      = (const float*)d_in[0];   // (B, N, D) fp32
    const int*   first_idx = (const int*)d_in[1];     // (B,) int32
    float*       out       = (float*)d_out;           // (B, K, D) fp32
    (void)in_sizes; (void)n_in; (void)out_size;

    cudaFuncSetAttribute(kmpp_phase2,
                         cudaFuncAttributeMaxDynamicSharedMemorySize,
                         SMEM2_BYTES);

    km_init<<<32, NT>>>();
    kmpp_phase1<<<NCTA, NT>>>(data, first_idx, out);
    kmpp_phase2<<<BB, NT2, SMEM2_BYTES>>>(data, out);
}

// round 17
// speedup vs baseline: 1.6257x; 1.6257x over previous
#include <cuda_runtime.h>
#include <cuda_bf16.h>

#define BB   32
#define NN   16384
#define DD   64
#define KK   64
#define CPB  8
#define NCTA (BB*CPB)                 // 256
#define NT   512
#define NW   16
#define PTS  2048                     // points per CTA
#define PPT  4                        // points per thread
#define CROW 65                       // padded center row (conflict-free)
#define KD   16                       // dense rounds: k <= KD update everything
#define PAIRCAP 3072                  // (point,center) pair buffer (12 KB)
#define SENT 0xFFFFFFFFu

// ---------------- device globals (static scratch only) --------------------
// One slot per (batch, round, chunk). The packed value IS the message
// (low word = ~idx != 0), so a single word store/poll synchronizes a round.
__device__ unsigned long long g_part[BB * KK * CPB];   // 128 KB

__global__ void km_init() {
    int i = blockIdx.x * blockDim.x + threadIdx.x;
    if (i < BB * KK * CPB) g_part[i] = 0ULL;
}

// 32-byte read-only global load (256-bit). Bits land unchanged.
__device__ __forceinline__ void ld256(const float* p, float4& a, float4& b) {
    unsigned long long x, y, z, w;
    asm("ld.global.nc.v4.b64 {%0,%1,%2,%3}, [%4];"
        : "=l"(x), "=l"(y), "=l"(z), "=l"(w) : "l"(p));
    a.x = __uint_as_float((unsigned)x);  a.y = __uint_as_float((unsigned)(x >> 32));
    a.z = __uint_as_float((unsigned)y);  a.w = __uint_as_float((unsigned)(y >> 32));
    b.x = __uint_as_float((unsigned)z);  b.y = __uint_as_float((unsigned)(z >> 32));
    b.z = __uint_as_float((unsigned)w);  b.w = __uint_as_float((unsigned)(w >> 32));
}

// ---- THE distance: R1's PROVEN rounding order (rel_err 0.0 since R7).
// Four sequential 16-dim fmaf chains, combined ((s0+s1)+s2)+s3.
__device__ __forceinline__ float dist16x4_g(const float* __restrict__ px,
                                            const float* __restrict__ cen) {
    float s[4];
    #pragma unroll
    for (int g = 0; g < 4; ++g) {
        float4 v0, v1, v2, v3;
        ld256(px + g * 16,     v0, v1);
        ld256(px + g * 16 + 8, v2, v3);
        const int b = g * 16;
        float acc = 0.f, d;
        d = v0.x - cen[b + 0];  acc = fmaf(d, d, acc);
        d = v0.y - cen[b + 1];  acc = fmaf(d, d, acc);
        d = v0.z - cen[b + 2];  acc = fmaf(d, d, acc);
        d = v0.w - cen[b + 3];  acc = fmaf(d, d, acc);
        d = v1.x - cen[b + 4];  acc = fmaf(d, d, acc);
        d = v1.y - cen[b + 5];  acc = fmaf(d, d, acc);
        d = v1.z - cen[b + 6];  acc = fmaf(d, d, acc);
        d = v1.w - cen[b + 7];  acc = fmaf(d, d, acc);
        d = v2.x - cen[b + 8];  acc = fmaf(d, d, acc);
        d = v2.y - cen[b + 9];  acc = fmaf(d, d, acc);
        d = v2.z - cen[b + 10]; acc = fmaf(d, d, acc);
        d = v2.w - cen[b + 11]; acc = fmaf(d, d, acc);
        d = v3.x - cen[b + 12]; acc = fmaf(d, d, acc);
        d = v3.y - cen[b + 13]; acc = fmaf(d, d, acc);
        d = v3.z - cen[b + 14]; acc = fmaf(d, d, acc);
        d = v3.w - cen[b + 15]; acc = fmaf(d, d, acc);
        s[g] = acc;
    }
    return ((s[0] + s[1]) + s[2]) + s[3];
}
__device__ __forceinline__ float dist16x4_s(const float* __restrict__ pt,
                                            const float* __restrict__ cen) {
    float s[4];
    #pragma unroll
    for (int g = 0; g < 4; ++g) {
        float acc = 0.f;
        #pragma unroll
        for (int i = 0; i < 16; ++i) {
            float d = pt[g * 16 + i] - cen[g * 16 + i];
            acc = fmaf(d, d, acc);
        }
        s[g] = acc;
    }
    return ((s[0] + s[1]) + s[2]) + s[3];
}

__device__ __forceinline__ unsigned long long warp_max_u64(unsigned long long v) {
    #pragma unroll
    for (int o = 16; o; o >>= 1) {
        unsigned long long u = __shfl_xor_sync(0xffffffffu, v, o);
        v = (v > u) ? v : u;
    }
    return v;
}
__device__ __forceinline__ float warp_min_f(float m) {
    #pragma unroll
    for (int o = 16; o; o >>= 1) m = fminf(m, __shfl_xor_sync(0xffffffffu, m, o));
    return m;
}

__global__ void __launch_bounds__(NT, 2)
kmpp_kernel(const float* __restrict__ data,
            const int*   __restrict__ first_idx,
            float*       __restrict__ out)
{
    __shared__ float s_c[KK][CROW];               // 16.6 KB: all centers
    __shared__ __align__(16) float s_ub[PTS];     //  8 KB: upper bounds on min_d
    __shared__ unsigned char s_lk[PTS];           //  2 KB: centers accounted
    __shared__ unsigned s_pairs[PAIRCAP];         // 12 KB: (p<<6|c) work items
    __shared__ __align__(16) float s_pt[NW][DD];  //  4 KB: per-warp staged point
    __shared__ unsigned long long s_red[NW];
    __shared__ unsigned long long s_parts[CPB];   // polled peer contributions
    __shared__ unsigned int s_Ebits;
    __shared__ int s_widx, s_paircnt;

    const int t     = threadIdx.x;
    const int lane  = t & 31;
    const int wid   = t >> 5;
    const int cta   = blockIdx.x;
    const int batch = cta / CPB;
    const int chunk = cta % CPB;
    const int pbase = chunk * PTS;
    const float* bd = data + (size_t)batch * NN * DD;
    float* bout     = out  + (size_t)batch * KK * DD;
    const bool leader = (chunk == 0);

    // center 0
    if (t < DD) {
        int i0 = first_idx[batch];
        float c = bd[(size_t)i0 * DD + t];
        s_c[0][t] = c;
        if (leader) bout[t] = c;
    }
    // ub = +inf; dense round k=1 produces d(x, c0) exactly (fmin(inf, d) = d)
    #pragma unroll
    for (int j = 0; j < PPT; ++j) {
        s_ub[t * PPT + j] = 3.4e38f;
        s_lk[t * PPT + j] = 1;
    }
    __syncthreads();

    // warp-cooperative dense mapping: lane -> (point-in-tile, dim group)
    const int pl = lane >> 2;          // 0..7
    const int g  = lane & 3;           // 0..3
    const int lb = lane & ~3;          // group-base lane for shfl gathers
    const float* wbase = bd + (size_t)(pbase + wid * 128) * DD;

    for (int k = 1; k < KK; ++k) {
        if (k <= KD) {
            // ======== DENSE (R15, unchanged): warp-cooperative sweep,
            // 256-bit loads, fused packed argmax. Runs at ~DRAM ceiling.
            const float* cen = &s_c[k - 1][g * 16];
            float cg[16];
            #pragma unroll
            for (int i = 0; i < 16; ++i) cg[i] = cen[i];

            unsigned long long best = 0ULL;
            #pragma unroll 2
            for (int it = 0; it < 16; ++it) {
                const int pt = it * 8 + pl;
                const float* px = wbase + (size_t)pt * DD + g * 16;
                float4 v0, v1, v2, v3;
                ld256(px,     v0, v1);
                ld256(px + 8, v2, v3);
                float acc = 0.f, d;
                d = v0.x - cg[0];  acc = fmaf(d, d, acc);
                d = v0.y - cg[1];  acc = fmaf(d, d, acc);
                d = v0.z - cg[2];  acc = fmaf(d, d, acc);
                d = v0.w - cg[3];  acc = fmaf(d, d, acc);
                d = v1.x - cg[4];  acc = fmaf(d, d, acc);
                d = v1.y - cg[5];  acc = fmaf(d, d, acc);
                d = v1.z - cg[6];  acc = fmaf(d, d, acc);
                d = v1.w - cg[7];  acc = fmaf(d, d, acc);
                d = v2.x - cg[8];  acc = fmaf(d, d, acc);
                d = v2.y - cg[9];  acc = fmaf(d, d, acc);
                d = v2.z - cg[10]; acc = fmaf(d, d, acc);
                d = v2.w - cg[11]; acc = fmaf(d, d, acc);
                d = v3.x - cg[12]; acc = fmaf(d, d, acc);
                d = v3.y - cg[13]; acc = fmaf(d, d, acc);
                d = v3.z - cg[14]; acc = fmaf(d, d, acc);
                d = v3.w - cg[15]; acc = fmaf(d, d, acc);
                float s0 = __shfl_sync(0xffffffffu, acc, lb + 0);
                float s1 = __shfl_sync(0xffffffffu, acc, lb + 1);
                float s2 = __shfl_sync(0xffffffffu, acc, lb + 2);
                float s3 = __shfl_sync(0xffffffffu, acc, lb + 3);
                float s  = ((s0 + s1) + s2) + s3;
                if (g == 0) {
                    int p = wid * 128 + pt;
                    float m = fminf(s_ub[p], s);   // winner ub=0 self-maintains
                    s_ub[p] = m;
                    unsigned long long pk =
                        ((unsigned long long)__float_as_uint(m) << 32) |
                        (unsigned)~(pbase + p);
                    best = (best > pk) ? best : pk;
                }
            }
            best = warp_max_u64(best);             // g!=0 lanes hold 0
            if (lane == 0) s_red[wid] = best;
        } else {
            // ======== FILTERED: candidate E + pair-expanded refresh.
            if (k == KD + 1) {
                #pragma unroll
                for (int j = 0; j < PPT; ++j) {
                    int p = t * PPT + j;
                    if (s_lk[p] != (unsigned char)KK) s_lk[p] = (unsigned char)KD;
                }
            }
            if (t == 0) { s_Ebits = 0u; s_paircnt = 0; }
            // clear pair buffer to sentinel (holes from failed reservations)
            #pragma unroll
            for (int i = t; i < PAIRCAP; i += NT) s_pairs[i] = SENT;
            __syncthreads();

            // (B) per-warp candidate: fully refresh the warp's max-ub point.
            //     E = max of 16 exact min_d values <= round winner value.
            {
                int base = wid * 128 + lane * 4;
                float4 u = *(const float4*)&s_ub[base];
                unsigned long long wb;
                {
                    unsigned long long p0 = ((unsigned long long)__float_as_uint(u.x) << 32) | (unsigned)~(base + 0);
                    unsigned long long p1 = ((unsigned long long)__float_as_uint(u.y) << 32) | (unsigned)~(base + 1);
                    unsigned long long p2 = ((unsigned long long)__float_as_uint(u.z) << 32) | (unsigned)~(base + 2);
                    unsigned long long p3 = ((unsigned long long)__float_as_uint(u.w) << 32) | (unsigned)~(base + 3);
                    wb = p0 > p1 ? p0 : p1;
                    wb = wb > p2 ? wb : p2;
                    wb = wb > p3 ? wb : p3;
                }
                wb = warp_max_u64(wb);
                int p = (int)(~(unsigned)wb) & (PTS - 1);

                if (lane < 16)
                    ((float4*)&s_pt[wid][0])[lane] =
                        __ldg(((const float4*)(bd + (size_t)(pbase + p) * DD)) + lane);
                __syncwarp();

                int   clk = s_lk[p];
                float m   = s_ub[p];
                for (int c = clk + lane; c < k; c += 32)
                    m = fminf(m, dist16x4_s(&s_pt[wid][0], &s_c[c][0]));
                m = warp_min_f(m);
                if (lane == 0) {
                    s_ub[p] = m;
                    if (clk < k) s_lk[p] = (unsigned char)k;
                    atomicMax(&s_Ebits, __float_as_uint(m));
                }
            }
            __syncthreads();
            const float E = __uint_as_float(s_Ebits);

            // (C1) classify: expand each hit into (p,c) pairs. Overflow ->
            // owner-serial catch-up (rare). Pruned points keep stale ub,
            // which is < E <= winner, so they can't affect the argmax.
            #pragma unroll
            for (int j = 0; j < PPT; ++j) {
                int p = t * PPT + j;
                float m = s_ub[p];
                int   c = s_lk[p];
                if (m >= E && c < k) {
                    int lag = k - c;
                    int base = atomicAdd(&s_paircnt, lag);
                    if (base + lag <= PAIRCAP) {
                        for (int cc = c; cc < k; ++cc)
                            s_pairs[base + (cc - c)] = ((unsigned)p << 6) | (unsigned)cc;
                    } else {
                        const float* px = bd + (size_t)(pbase + p) * DD;
                        for (; c < k; ++c)
                            m = fminf(m, dist16x4_g(px, &s_c[c][0]));
                        s_ub[p] = m;
                    }
                    s_lk[p] = (unsigned char)k;
                }
            }
            __syncthreads();

            // (C2) process pairs, perfectly load-balanced. atomicMin on the
            // bit pattern == fminf for nonneg floats (order-independent).
            const int C = min(s_paircnt, PAIRCAP);
            for (int i = t; i < C; i += NT) {
                unsigned e = s_pairs[i];
                if (e != SENT) {
                    int p = (int)(e >> 6);
                    int c = (int)(e & 63u);
                    float d = dist16x4_g(bd + (size_t)(pbase + p) * DD, &s_c[c][0]);
                    atomicMin((unsigned*)&s_ub[p], __float_as_uint(d));
                }
            }
            __syncthreads();

            // (D) full packed-argmax rescan (refreshed values are final)
            unsigned long long best = 0ULL;
            #pragma unroll
            for (int j = 0; j < PPT; ++j) {
                int p = t * PPT + j;
                unsigned long long pk =
                    ((unsigned long long)__float_as_uint(s_ub[p]) << 32) |
                    (unsigned)~(pbase + p);
                best = (best > pk) ? best : pk;
            }
            best = warp_max_u64(best);
            if (lane == 0) s_red[wid] = best;
        }

        // ======== tail: single-word broadcast barrier, select winner
        __syncthreads();
        if (t == 0) {
            unsigned long long b = s_red[0];
            #pragma unroll
            for (int i = 1; i < NW; ++i) b = (b > s_red[i]) ? b : s_red[i];
            atomicExch(&g_part[(batch * KK + k) * CPB + chunk], b);
        }
        if (t < CPB) {
            volatile unsigned long long* sp =
                (volatile unsigned long long*)&g_part[(batch * KK + k) * CPB + t];
            unsigned long long v;
            while ((v = *sp) == 0ULL) { __nanosleep(32); }
            s_parts[t] = v;
        }
        __syncthreads();
        if (t == 0) {
            unsigned long long b = s_parts[0];
            #pragma unroll
            for (int i = 1; i < CPB; ++i) b = (b > s_parts[i]) ? b : s_parts[i];
            s_widx = (int)(~(unsigned)b);
        }
        __syncthreads();

        // (E) gather winner as center k; zero its bound locally
        int w = s_widx;
        if (t < DD) {
            float c = bd[(size_t)w * DD + t];
            s_c[k][t] = c;
            if (leader) bout[k * DD + t] = c;
        }
        if (t == NT - 1) {
            int wl = w - pbase;
            if (wl >= 0 && wl < PTS) { s_ub[wl] = 0.f; s_lk[wl] = (unsigned char)KK; }
        }
        __syncthreads();
    }
}

extern "C" void kernel_launch(void* const* d_in, const int* in_sizes, int n_in,
                              void* d_out, int out_size) {
    const float* data      = (const float*)d_in[0];   // (B, N, D) fp32
    const int*   first_idx = (const int*)d_in[1];     // (B,) int32
    float*       out       = (float*)d_out;           // (B, K, D) fp32
    (void)in_sizes; (void)n_in; (void)out_size;
    km_init<<<32, NT>>>();
    kmpp_kernel<<<NCTA, NT>>>(data, first_idx, out);
}